// round 14
// baseline (speedup 1.0000x reference)
#include <cuda_runtime.h>
#include <math.h>

#define NSEQ   1024   // B*LC token-level sequences
#define TSTEPS 64     // token time steps
#define EDIM   300
#define HDIM   256
#define BATCH  32
#define LCH    32
#define NTAG   9
#define TOK_CTAS 256
#define CHK_CTAS 32

typedef unsigned long long u64;

// ---------------- scratch (__device__ globals; no allocations allowed) ----------------
__device__ float g_WtI[EDIM * 1024];       // token fwd INPUT weights, [k][j], j = gate*256+u
__device__ float g_WtR[HDIM * 1024];       // token fwd RECURRENT weights, [k][j]
__device__ float g_WtB[EDIM * 1024];       // token bwd input weights, [k][j]
__device__ float g_WtCin[512 * 2048];      // chunk input weights, [k][d*1024+j]
__device__ float g_WtChh[2][256 * 1024];   // chunk recurrent weights per dir, [k][j]

__device__ float g_gx[(size_t)TSTEPS * 1024 * 1024]; // input proj + bias (sorted rows)
__device__ float g_hf[2][NSEQ * HDIM];     // token fwd h, double buffered (sorted order)
__device__ float g_tok_last[NSEQ * 512];   // [n][hf_last | hb_last]  (original order)
__device__ float g_gxc[NSEQ * 2048];       // chunk input projection [row][d*1024+j]
__device__ float g_chh[2][2][BATCH * HDIM];// chunk h per dir, double buffered
__device__ float g_chout[NSEQ * 512];      // chunk BiLSTM outputs [b*32+t][hf|hb]

__device__ int g_order[NSEQ];              // sorted pos p -> original seq n
__device__ int g_sclen[NSEQ];              // clen at sorted pos p
__device__ int g_clen[NSEQ];               // clen in original order
__device__ int g_active[TSTEPS];           // #rows with clen > t

__device__ unsigned g_tok_bar;             // persistent-kernel barrier tickets
__device__ unsigned g_chk_bar;

// row-group permutation: bids b and b+148 share an SM; pair lifetimes balanced,
// solo indices get the shortest-lived tiles.
__device__ __constant__ int c_perm[16] = {0,1,2,3,4,5,6,15,14,13,12,11,10,9,8,7};

__device__ __forceinline__ float sigf(float x) { return 1.f / (1.f + expf(-x)); }

// f32x2 packed helpers (sm_103a FFMA2 path, PTX-only)
__device__ __forceinline__ void ffma2(u64& d, u64 a, u64 b) {
    asm("fma.rn.f32x2 %0, %1, %2, %0;" : "+l"(d) : "l"(a), "l"(b));
}
__device__ __forceinline__ u64 pack2(float lo, float hi) {
    u64 v; asm("mov.b64 %0, {%1, %2};" : "=l"(v) : "f"(lo), "f"(hi)); return v;
}
__device__ __forceinline__ void unpack2(u64 v, float& lo, float& hi) {
    asm("mov.b64 {%0, %1}, %2;" : "=f"(lo), "=f"(hi) : "l"(v));
}

// ---------------- weight transpose: make K the slow axis ----------------
#define PW_S1 (EDIM * 1024)                       // WtI
#define PW_S2 (PW_S1 + HDIM * 1024)               // WtR
#define PW_S3 (PW_S2 + EDIM * 1024)               // WtB
#define PW_S4 (PW_S3 + 512 * 2048)                // WtCin
#define PW_TOT (PW_S4 + 2 * 256 * 1024)           // WtChh

__global__ void prep_weights(const float* __restrict__ WihF, const float* __restrict__ WhhF,
                             const float* __restrict__ WihB,
                             const float* __restrict__ WihCf, const float* __restrict__ WihCb,
                             const float* __restrict__ WhhCf, const float* __restrict__ WhhCb)
{
    int stride = gridDim.x * blockDim.x;
    for (int idx = blockIdx.x * blockDim.x + threadIdx.x; idx < PW_TOT; idx += stride) {
        if (idx < PW_S1) {
            int k = idx >> 10, j = idx & 1023;
            g_WtI[idx] = WihF[j * EDIM + k];
        } else if (idx < PW_S2) {
            int r = idx - PW_S1;
            int k = r >> 10, j = r & 1023;
            g_WtR[r] = WhhF[j * HDIM + k];
        } else if (idx < PW_S3) {
            int r = idx - PW_S2;
            int k = r >> 10, j = r & 1023;
            g_WtB[r] = WihB[j * EDIM + k];
        } else if (idx < PW_S4) {
            int r = idx - PW_S3;
            int k = r >> 11, col = r & 2047;
            int d = col >> 10, j = col & 1023;
            g_WtCin[r] = (d ? WihCb : WihCf)[j * 512 + k];
        } else {
            int r = idx - PW_S4;
            int d = r >> 18;
            int rr = r & ((1 << 18) - 1);
            int k = rr >> 10, j = rr & 1023;
            g_WtChh[d][rr] = (d ? WhhCb : WhhCf)[j * HDIM + k];
        }
    }
}

// ---------------- counting sort by descending clen ----------------
__global__ void sort_kernel(const int* __restrict__ x_chunk_len)
{
    __shared__ int cnt[65];
    __shared__ int start[65];
    int tid = threadIdx.x;
    if (tid < 65) cnt[tid] = 0;
    __syncthreads();
    int c = x_chunk_len[tid];
    c = min(max(c, 1), TSTEPS);
    g_clen[tid] = c;
    atomicAdd(&cnt[c], 1);
    __syncthreads();
    if (tid == 0) {
        int s = 0;
        for (int v = TSTEPS; v >= 1; --v) { start[v] = s; s += cnt[v]; }
        g_active[0] = NSEQ;
        for (int t = 1; t < TSTEPS; ++t) g_active[t] = start[t];
    }
    __syncthreads();
    if (tid < 65) cnt[tid] = 0;
    __syncthreads();
    int p = start[c] + atomicAdd(&cnt[c], 1);
    g_order[p] = tid;
    g_sclen[p] = c;
}

// ---------------- zero state buffers (every call: graph replays) ----------
__global__ void init_zero()
{
    int idx0 = blockIdx.x * blockDim.x + threadIdx.x;
    int stride = gridDim.x * blockDim.x;
    if (idx0 == 0) { g_tok_bar = 0u; g_chk_bar = 0u; }
    float* h0 = &g_hf[0][0];
    for (int i = idx0; i < 2 * NSEQ * HDIM; i += stride) h0[i] = 0.f;
    float* ch = &g_chh[0][0][0];
    for (int i = idx0; i < 2 * 2 * BATCH * HDIM; i += stride) ch[i] = 0.f;
}

// ---------------- gx = emb[x] @ WihF^T + b  (FFMA2, dup-A, conflict-free B) -----------
// tile 64 rows x 128 cols; thread: 4 rows x 4 col-pairs (cols 2tx+32j).
// A stored PRE-DUPLICATED as (a,a) u64 -> inner loop has zero pack-MOVs.
// B kept in R12's float layout: u64 reads at 8B lane stride (conflict-free).
__global__ void __launch_bounds__(256, 4) gx_gemm(
    const int* __restrict__ x, const float* __restrict__ emb,
    const float* __restrict__ bias)
{
    int t = blockIdx.z;
    int act = g_active[t];
    int row0 = blockIdx.y * 64;
    if (row0 >= act) return;
    int c0 = blockIdx.x * 128;

    __shared__ int s_tok[64];
    __shared__ u64 As2[64 * 33];     // 16.9KB, (a,a) duplicated
    __shared__ float Bs[32][128];    // 16KB

    int tid = threadIdx.x;
    if (tid < 64) {
        int n = g_order[row0 + tid];
        s_tok[tid] = x[n * TSTEPS + t];
    }
    __syncthreads();

    int tx = tid & 15, ty = tid >> 4;
    u64 acc[4][4];
#pragma unroll
    for (int i = 0; i < 4; i++)
#pragma unroll
        for (int j = 0; j < 4; j++) acc[i][j] = 0ull;

    for (int k0 = 0; k0 < EDIM; k0 += 32) {
        // A: 64 rows x 16 k-pairs (float2 gather) -> duplicated u64 pairs
        // (STS64 lane stride 16B: 2-way worst case, amortized over the k-loop)
#pragma unroll
        for (int i = 0; i < 4; i++) {
            int idx = tid + i * 256;
            int r = idx >> 4, kp = idx & 15;
            int kg = k0 + 2 * kp;
            float2 v = make_float2(0.f, 0.f);
            if (kg < EDIM) v = *(const float2*)&emb[(size_t)s_tok[r] * EDIM + kg];
            As2[r * 33 + 2 * kp]     = pack2(v.x, v.x);
            As2[r * 33 + 2 * kp + 1] = pack2(v.y, v.y);
        }
        // B: 32 k x 64 col-pairs (float2), R12 layout
#pragma unroll
        for (int i = 0; i < 8; i++) {
            int idx = tid + i * 256;
            int k = idx >> 6, cp = idx & 63;
            int kg = k0 + k;
            float2 v = make_float2(0.f, 0.f);
            if (kg < EDIM) v = *(const float2*)&g_WtI[kg * 1024 + c0 + 2 * cp];
            Bs[k][2 * cp] = v.x;
            Bs[k][2 * cp + 1] = v.y;
        }
        __syncthreads();
#pragma unroll 4
        for (int k = 0; k < 32; k++) {
            u64 a2[4];
#pragma unroll
            for (int i = 0; i < 4; i++) a2[i] = As2[(4 * ty + i) * 33 + k];
#pragma unroll
            for (int j = 0; j < 4; j++) {
                u64 w = *(const u64*)&Bs[k][2 * tx + 32 * j];
#pragma unroll
                for (int i = 0; i < 4; i++) ffma2(acc[i][j], a2[i], w);
            }
        }
        __syncthreads();
    }
#pragma unroll
    for (int i = 0; i < 4; i++) {
        int row = row0 + 4 * ty + i;
        float* dst = &g_gx[((size_t)t * 1024 + row) * 1024];
#pragma unroll
        for (int j = 0; j < 4; j++) {
            int col = c0 + 2 * tx + 32 * j;
            float lo, hi; unpack2(acc[i][j], lo, hi);
            *(float2*)&dst[col] = make_float2(lo + bias[col], hi + bias[col + 1]);
        }
    }
}

// ---------------- PERSISTENT token forward recurrence: 256 CTAs, 2/SM -----------------
// (exact R12 structure: known-good 20us/step)
__global__ void __launch_bounds__(256, 2) tok_persist()
{
    extern __shared__ u64 smdyn[];
    u64* ws = smdyn;                               // [k 256][combo 32] u64 = 64KB
    float* Asm = (float*)(smdyn + 8192);           // [2][64][36] h tiles (18.4KB)
    float* stage = Asm + 2 * 64 * 36;              // [64][68] gate staging (17.4KB)

    int cb = blockIdx.x & 15;
    int rg = c_perm[blockIdx.x >> 4];
    int row0 = rg * 64;
    int u0 = cb * 16;
    int tid = threadIdx.x;
    int ty4 = tid >> 4;        // 0..15 -> rows ty4*4..+3
    int txc = tid & 15;        // combos 2txc, 2txc+1

    // load weight pairs once: ws[k*32 + c], c=(g<<3)|up -> (W[k][g*256+u0+2up], +1)
    for (int idx = tid; idx < 8192; idx += 256) {
        int k = idx >> 5, c = idx & 31, g = c >> 3, up = c & 7;
        const float* sp = &g_WtR[k * 1024 + g * 256 + u0 + 2 * up];
        ws[idx] = pack2(sp[0], sp[1]);
    }
    // c-state registers, keyed to epilogue mapping: row=tid>>2, u-quad (tid&3)*4
    float creg[4];
#pragma unroll
    for (int j = 0; j < 4; j++) creg[j] = 0.f;
    __syncthreads();

    for (int t = 0; t < TSTEPS; t++) {
        int act = g_active[t];
        if (row0 < act) {
            const float* __restrict__ hin = g_hf[t & 1];
            float* __restrict__ hout = g_hf[(t + 1) & 1];
            const float* __restrict__ gxt = &g_gx[(size_t)t * 1024 * 1024];

            u64 acc[4][2];
#pragma unroll
            for (int i = 0; i < 4; i++) { acc[i][0] = 0ull; acc[i][1] = 0ull; }

            // prefetch k-tile 0: 64 rows x 32 k
#pragma unroll
            for (int i = 0; i < 2; i++) {
                int idx = tid + i * 256;
                int r = idx >> 3, kq = idx & 7;
                float4 v = __ldcg((const float4*)&hin[(row0 + r) * HDIM + kq * 4]);
                *(float4*)&Asm[r * 36 + kq * 4] = v;
            }
            __syncthreads();

#pragma unroll 1
            for (int kt = 0; kt < 8; kt++) {
                float4 nxt[2];
                if (kt < 7) {
#pragma unroll
                    for (int i = 0; i < 2; i++) {
                        int idx = tid + i * 256;
                        int r = idx >> 3, kq = idx & 7;
                        nxt[i] = __ldcg((const float4*)&hin[(row0 + r) * HDIM + (kt + 1) * 32 + kq * 4]);
                    }
                }
                const float* Ab = &Asm[(kt & 1) * (64 * 36)];
                const u64* wk = &ws[kt * 1024];
#pragma unroll 8
                for (int kk = 0; kk < 32; kk++) {
                    u64 a2[4];
#pragma unroll
                    for (int i = 0; i < 4; i++) {
                        float a = Ab[(ty4 * 4 + i) * 36 + kk];
                        a2[i] = pack2(a, a);
                    }
                    ulonglong2 w2 = *(const ulonglong2*)&wk[kk * 32 + 2 * txc];
#pragma unroll
                    for (int i = 0; i < 4; i++) {
                        ffma2(acc[i][0], a2[i], w2.x);
                        ffma2(acc[i][1], a2[i], w2.y);
                    }
                }
                if (kt < 7) {
                    float* d0 = &Asm[((kt + 1) & 1) * (64 * 36)];
#pragma unroll
                    for (int i = 0; i < 2; i++) {
                        int idx = tid + i * 256;
                        int r = idx >> 3, kq = idx & 7;
                        *(float4*)&d0[r * 36 + kq * 4] = nxt[i];
                    }
                }
                __syncthreads();
            }

            // stage: stage[row][g*16 + up*2] <- acc pairs
#pragma unroll
            for (int j = 0; j < 2; j++) {
                int c = 2 * txc + j;
                int g = c >> 3, up = c & 7;
                int col = g * 16 + up * 2;
#pragma unroll
                for (int i = 0; i < 4; i++)
                    *(u64*)&stage[(ty4 * 4 + i) * 68 + col] = acc[i][j];
            }
            __syncthreads();

            // epilogue: thread -> row tid>>2, u-quad (tid&3)*4
            {
                int erow = tid >> 2;
                int p = row0 + erow;
                if (p < act) {
                    int uq = (tid & 3) * 4;
                    float4 gi4 = *(const float4*)&stage[erow * 68 + 0 * 16 + uq];
                    float4 gf4 = *(const float4*)&stage[erow * 68 + 1 * 16 + uq];
                    float4 gg4 = *(const float4*)&stage[erow * 68 + 2 * 16 + uq];
                    float4 go4 = *(const float4*)&stage[erow * 68 + 3 * 16 + uq];
                    const float* gxr = &gxt[(size_t)p * 1024];
                    float4 bi = *(const float4*)&gxr[u0 + uq];
                    float4 bf = *(const float4*)&gxr[256 + u0 + uq];
                    float4 bg = *(const float4*)&gxr[512 + u0 + uq];
                    float4 bo = *(const float4*)&gxr[768 + u0 + uq];
                    float gi[4] = {gi4.x + bi.x, gi4.y + bi.y, gi4.z + bi.z, gi4.w + bi.w};
                    float gf[4] = {gf4.x + bf.x, gf4.y + bf.y, gf4.z + bf.z, gf4.w + bf.w};
                    float gg[4] = {gg4.x + bg.x, gg4.y + bg.y, gg4.z + bg.z, gg4.w + bg.w};
                    float go[4] = {go4.x + bo.x, go4.y + bo.y, go4.z + bo.z, go4.w + bo.w};
                    float4 hn;
                    float* hv = (float*)&hn;
#pragma unroll
                    for (int j = 0; j < 4; j++) {
                        float cn = sigf(gf[j]) * creg[j] + sigf(gi[j]) * tanhf(gg[j]);
                        hv[j] = sigf(go[j]) * tanhf(cn);
                        creg[j] = cn;
                    }
                    *(float4*)&hout[p * HDIM + u0 + uq] = hn;
                }
            }
        }

        // grid-wide barrier (skip after last step)
        if (t < TSTEPS - 1) {
            __threadfence();
            __syncthreads();
            if (tid == 0) {
                atomicAdd(&g_tok_bar, 1u);
                unsigned target = (unsigned)(t + 1) * TOK_CTAS;
                while (*((volatile unsigned*)&g_tok_bar) < target) {}
            }
            __syncthreads();
        }
    }
}

// ---------------- token backward = ONE step from zero state at t = clen-1 -------------
__global__ void __launch_bounds__(256) tok_bwd(
    const int* __restrict__ x, const float* __restrict__ emb,
    const float* __restrict__ bias)
{
    int row0 = blockIdx.x * 32;
    int u0 = blockIdx.y * 64;
    __shared__ float As[32][33];
    __shared__ float Ws[4][32][64];
    __shared__ int s_tok[32];
    int tid = threadIdx.x;
    if (tid < 32) {
        int n = row0 + tid;
        int c = g_clen[n];
        s_tok[tid] = x[n * TSTEPS + (c - 1)];
    }
    __syncthreads();
    int tx = tid & 15, ty = tid >> 4;
    float acc[2][4][4];
#pragma unroll
    for (int r = 0; r < 2; r++)
#pragma unroll
        for (int q = 0; q < 4; q++)
#pragma unroll
            for (int j = 0; j < 4; j++) acc[r][q][j] = 0.f;

    for (int k0 = 0; k0 < EDIM; k0 += 32) {
#pragma unroll
        for (int i = 0; i < 4; i++) {
            int idx = tid + i * 256;
            int r = idx >> 5, kl = idx & 31;
            int kg = k0 + kl;
            As[r][kl] = (kg < EDIM) ? emb[(size_t)s_tok[r] * EDIM + kg] : 0.f;
        }
#pragma unroll
        for (int i = 0; i < 32; i++) {
            int idx = tid + i * 256;
            int q = idx >> 11;
            int rem = idx & 2047;
            int kl = rem >> 6, u = rem & 63;
            int kg = k0 + kl;
            Ws[q][kl][u] = (kg < EDIM) ? g_WtB[kg * 1024 + q * 256 + u0 + u] : 0.f;
        }
        __syncthreads();
#pragma unroll
        for (int k = 0; k < 32; k++) {
            float a0 = As[2 * ty][k];
            float a1 = As[2 * ty + 1][k];
#pragma unroll
            for (int q = 0; q < 4; q++) {
                float4 w = *(const float4*)&Ws[q][k][tx * 4];
                acc[0][q][0] += a0 * w.x; acc[0][q][1] += a0 * w.y;
                acc[0][q][2] += a0 * w.z; acc[0][q][3] += a0 * w.w;
                acc[1][q][0] += a1 * w.x; acc[1][q][1] += a1 * w.y;
                acc[1][q][2] += a1 * w.z; acc[1][q][3] += a1 * w.w;
            }
        }
        __syncthreads();
    }

#pragma unroll
    for (int rr = 0; rr < 2; rr++) {
        int n = row0 + 2 * ty + rr;
#pragma unroll
        for (int j = 0; j < 4; j++) {
            int u = u0 + tx * 4 + j;
            float gi = acc[rr][0][j] + bias[u];
            float gg = acc[rr][2][j] + bias[512 + u];
            float go = acc[rr][3][j] + bias[768 + u];
            float cn = sigf(gi) * tanhf(gg);
            float hn = sigf(go) * tanhf(cn);
            g_tok_last[n * 512 + 256 + u] = hn;
        }
    }
}

// ---------------- scatter forward finals back to original order ----------------------
__global__ void tok_fwd_readout()
{
    int p = blockIdx.x;
    int u = threadIdx.x;
    int n = g_order[p];
    int cl = g_sclen[p];
    g_tok_last[n * 512 + u] = g_hf[cl & 1][p * HDIM + u];
}

// ---------------- chunk-level input projection: [1024,512] x [512,2048] --------------
__global__ void __launch_bounds__(256) chunk_inproj(
    const float* __restrict__ bcf, const float* __restrict__ bcb)
{
    int row0 = blockIdx.x * 64;
    int c0 = blockIdx.y * 64;
    __shared__ float As[64][17];
    __shared__ float Bs[16][64];
    int tid = threadIdx.x;
    int tx = tid & 15, ty = tid >> 4;
    float acc[4][4];
#pragma unroll
    for (int i = 0; i < 4; i++)
#pragma unroll
        for (int j = 0; j < 4; j++) acc[i][j] = 0.f;

    for (int k0 = 0; k0 < 512; k0 += 16) {
#pragma unroll
        for (int i = 0; i < 4; i++) {
            int idx = tid + i * 256;
            int r = idx >> 4, kl = idx & 15;
            As[r][kl] = g_tok_last[(row0 + r) * 512 + k0 + kl];
        }
#pragma unroll
        for (int i = 0; i < 4; i++) {
            int idx = tid + i * 256;
            int kl = idx >> 6, c = idx & 63;
            Bs[kl][c] = g_WtCin[(k0 + kl) * 2048 + c0 + c];
        }
        __syncthreads();
#pragma unroll
        for (int k = 0; k < 16; k++) {
            float a[4];
#pragma unroll
            for (int i = 0; i < 4; i++) a[i] = As[4 * ty + i][k];
            float4 w = *(const float4*)&Bs[k][tx * 4];
#pragma unroll
            for (int i = 0; i < 4; i++) {
                acc[i][0] += a[i] * w.x; acc[i][1] += a[i] * w.y;
                acc[i][2] += a[i] * w.z; acc[i][3] += a[i] * w.w;
            }
        }
        __syncthreads();
    }
#pragma unroll
    for (int i = 0; i < 4; i++) {
        int row = row0 + 4 * ty + i;
#pragma unroll
        for (int j = 0; j < 4; j++) {
            int col = c0 + tx * 4 + j;
            int jj = col & 1023;
            float b = (col >> 10) ? bcb[jj] : bcf[jj];
            g_gxc[row * 2048 + col] = acc[i][j] + b;
        }
    }
}

// ---------------- PERSISTENT chunk BiLSTM (weights smem-resident, FFMA2) --------------
__global__ void __launch_bounds__(256) chunk_persist(const int* __restrict__ x_len)
{
    extern __shared__ u64 smdyn[];
    u64* ws = smdyn;                       // [k][g][up] (64KB)
    float* Asm = (float*)(smdyn + 8192);   // [32][257] full h (32.9KB)

    int d = blockIdx.x >> 4;
    int cb = blockIdx.x & 15;
    int u0 = cb * 16;
    int tid = threadIdx.x;
    int tx = tid & 7;
    int ty = tid >> 3;    // batch row 0..31

    for (int idx = tid; idx < 8192; idx += 256) {
        int k = idx >> 5, rem = idx & 31, g = rem >> 3, up = rem & 7;
        const float* sp = &g_WtChh[d][k * 1024 + g * 256 + u0 + 2 * up];
        ws[idx] = pack2(sp[0], sp[1]);
    }
    int len = x_len[ty];
    float c0r = 0.f, c1r = 0.f;
    __syncthreads();

    for (int s = 0; s < LCH; s++) {
        int t_d = d ? (LCH - 1 - s) : s;
        const float* __restrict__ hin = g_chh[d][s & 1];
        float* __restrict__ hout = g_chh[d][(s + 1) & 1];

#pragma unroll
        for (int i = 0; i < 8; i++) {
            int idx = tid + i * 256;
            int b = idx >> 6, kq = idx & 63;
            float4 v = __ldcg((const float4*)&hin[b * HDIM + kq * 4]);
            float* dp = &Asm[b * 257 + kq * 4];
            dp[0] = v.x; dp[1] = v.y; dp[2] = v.z; dp[3] = v.w;
        }
        __syncthreads();

        u64 acc[4] = {0ull, 0ull, 0ull, 0ull};
#pragma unroll 8
        for (int k = 0; k < 256; k++) {
            float a = Asm[ty * 257 + k];
            u64 a2 = pack2(a, a);
#pragma unroll
            for (int g = 0; g < 4; g++) ffma2(acc[g], a2, ws[k * 32 + g * 8 + tx]);
        }

        int ub = u0 + 2 * tx;
        bool actv = (t_d < len);
        float gi0, gi1, gf0, gf1, gg0, gg1, go0, go1;
        unpack2(acc[0], gi0, gi1);
        unpack2(acc[1], gf0, gf1);
        unpack2(acc[2], gg0, gg1);
        unpack2(acc[3], go0, go1);
        const float* gxr = &g_gxc[(ty * LCH + t_d) * 2048 + d * 1024];
        float2 bi = *(const float2*)&gxr[ub];
        float2 bf = *(const float2*)&gxr[256 + ub];
        float2 bg = *(const float2*)&gxr[512 + ub];
        float2 bo = *(const float2*)&gxr[768 + ub];
        gi0 += bi.x; gi1 += bi.y; gf0 += bf.x; gf1 += bf.y;
        gg0 += bg.x; gg1 += bg.y; go0 += bo.x; go1 += bo.y;
        float hp0 = Asm[ty * 257 + ub], hp1 = Asm[ty * 257 + ub + 1];
        float hn0 = hp0, hn1 = hp1, o0 = 0.f, o1 = 0.f;
        if (actv) {
            float cn0 = sigf(gf0) * c0r + sigf(gi0) * tanhf(gg0);
            float cn1 = sigf(gf1) * c1r + sigf(gi1) * tanhf(gg1);
            hn0 = sigf(go0) * tanhf(cn0);
            hn1 = sigf(go1) * tanhf(cn1);
            c0r = cn0; c1r = cn1;
            o0 = hn0; o1 = hn1;
        }
        *(float2*)&hout[ty * HDIM + ub] = make_float2(hn0, hn1);
        *(float2*)&g_chout[(ty * LCH + t_d) * 512 + d * 256 + ub] = make_float2(o0, o1);

        if (s < LCH - 1) {
            __threadfence();
            __syncthreads();
            if (tid == 0) {
                atomicAdd(&g_chk_bar, 1u);
                unsigned target = (unsigned)(s + 1) * CHK_CTAS;
                while (*((volatile unsigned*)&g_chk_bar) < target) {}
            }
            __syncthreads();
        }
    }
}

// ---------------- final FC: [1024,512] x [512,9] -------------------------------------
__global__ void fc_kernel(const float* __restrict__ fcW, const float* __restrict__ fcb,
                          float* __restrict__ out)
{
    int row = blockIdx.x * 8 + (threadIdx.x >> 5);
    int lane = threadIdx.x & 31;
    if (row >= NSEQ) return;
    const float* v = &g_chout[row * 512];
#pragma unroll
    for (int k = 0; k < NTAG; k++) {
        float sum = 0.f;
        for (int dd = lane; dd < 512; dd += 32) sum += v[dd] * fcW[k * 512 + dd];
#pragma unroll
        for (int o = 16; o; o >>= 1) sum += __shfl_xor_sync(0xffffffffu, sum, o);
        if (lane == 0) out[row * NTAG + k] = sum + fcb[k];
    }
}

// ---------------- launch --------------------------------------------------------------
#define TOK_SMEM (65536 + 2 * 64 * 36 * 4 + 64 * 68 * 4)   // 101376 (x2 = 198K < 228K/SM)
#define CHK_SMEM (65536 + 32 * 257 * 4)                    // 98432

extern "C" void kernel_launch(void* const* d_in, const int* in_sizes, int n_in,
                              void* d_out, int out_size)
{
    const int*   x           = (const int*)d_in[0];
    const int*   x_len       = (const int*)d_in[2];
    const int*   x_chunk_len = (const int*)d_in[3];
    const float* emb         = (const float*)d_in[4];
    const float* tok_Wih_f   = (const float*)d_in[5];
    const float* tok_Whh_f   = (const float*)d_in[6];
    const float* tok_b_f     = (const float*)d_in[7];
    const float* tok_Wih_b   = (const float*)d_in[8];
    const float* tok_b_b     = (const float*)d_in[10];
    const float* chk_Wih_f   = (const float*)d_in[11];
    const float* chk_Whh_f   = (const float*)d_in[12];
    const float* chk_b_f     = (const float*)d_in[13];
    const float* chk_Wih_b   = (const float*)d_in[14];
    const float* chk_Whh_b   = (const float*)d_in[15];
    const float* chk_b_b     = (const float*)d_in[16];
    const float* fc_W        = (const float*)d_in[17];
    const float* fc_b        = (const float*)d_in[18];
    float* out = (float*)d_out;

    cudaFuncSetAttribute(tok_persist, cudaFuncAttributeMaxDynamicSharedMemorySize, TOK_SMEM);
    cudaFuncSetAttribute(chunk_persist, cudaFuncAttributeMaxDynamicSharedMemorySize, CHK_SMEM);

    prep_weights<<<2048, 256>>>(tok_Wih_f, tok_Whh_f, tok_Wih_b,
                                chk_Wih_f, chk_Wih_b, chk_Whh_f, chk_Whh_b);
    sort_kernel<<<1, 1024>>>(x_chunk_len);
    init_zero<<<512, 256>>>();

    // Input projections for all active (row, t) pairs (parallel over t).
    gx_gemm<<<dim3(8, 16, 64), 256>>>(x, emb, tok_b_f);

    // Entire 64-step forward recurrence: 256 CTAs, 2/SM, one 64-row tile each.
    tok_persist<<<TOK_CTAS, 256, TOK_SMEM>>>();

    tok_fwd_readout<<<NSEQ, 256>>>();
    tok_bwd<<<dim3(32, 4), 256>>>(x, emb, tok_b_b);

    chunk_inproj<<<dim3(16, 32), 256>>>(chk_b_f, chk_b_b);

    // Entire 32-step chunk BiLSTM (both dirs) in ONE persistent kernel.
    chunk_persist<<<CHK_CTAS, 256, CHK_SMEM>>>(x_len);

    fc_kernel<<<128, 256>>>(fc_W, fc_b, out);
}

// round 15
// speedup vs baseline: 1.8254x; 1.8254x over previous
#include <cuda_runtime.h>
#include <math.h>

#define NSEQ   1024   // B*LC token-level sequences
#define TSTEPS 64     // token time steps
#define EDIM   300
#define HDIM   256
#define BATCH  32
#define LCH    32
#define NTAG   9
#define TOK_CTAS 256
#define CHK_CTAS 32

typedef unsigned long long u64;

// ---------------- scratch (__device__ globals; no allocations allowed) ----------------
__device__ float g_WtI[EDIM * 1024];       // token fwd INPUT weights, [k][j], j = gate*256+u
__device__ float g_WtR[HDIM * 1024];       // token fwd RECURRENT weights, [k][j]
__device__ float g_WtB[EDIM * 1024];       // token bwd input weights, [k][j]
__device__ float g_WtCin[512 * 2048];      // chunk input weights, [k][d*1024+j]
__device__ float g_WtChh[2][256 * 1024];   // chunk recurrent weights per dir, [k][j]

__device__ float g_gx[(size_t)TSTEPS * 1024 * 1024]; // input proj + bias (sorted rows)
__device__ float g_hf[2][NSEQ * HDIM];     // token fwd h, double buffered (sorted order)
__device__ float g_tok_last[NSEQ * 512];   // [n][hf_last | hb_last]  (original order)
__device__ float g_gxc[NSEQ * 2048];       // chunk input projection [row][d*1024+j]
__device__ float g_chh[2][2][BATCH * HDIM];// chunk h per dir, double buffered
__device__ float g_chout[NSEQ * 512];      // chunk BiLSTM outputs [b*32+t][hf|hb]

__device__ int g_order[NSEQ];              // sorted pos p -> original seq n
__device__ int g_sclen[NSEQ];              // clen at sorted pos p
__device__ int g_clen[NSEQ];               // clen in original order
__device__ int g_active[TSTEPS];           // #rows with clen > t

__device__ unsigned g_rg_bar[16];          // per-row-group barrier tickets (16 CTAs each)
__device__ unsigned g_chk_bar[2];          // per-direction barrier tickets (16 CTAs each)

// row-group permutation: bids b and b+148 share an SM; pair lifetimes balanced,
// solo indices get the shortest-lived tiles. After a short-lived tile dies, its
// CTA exits and the partner runs solo on the SM.
__device__ __constant__ int c_perm[16] = {0,1,2,3,4,5,6,15,14,13,12,11,10,9,8,7};

__device__ __forceinline__ float sigf(float x) { return 1.f / (1.f + expf(-x)); }

// f32x2 packed helpers (sm_103a FFMA2 path, PTX-only)
__device__ __forceinline__ void ffma2(u64& d, u64 a, u64 b) {
    asm("fma.rn.f32x2 %0, %1, %2, %0;" : "+l"(d) : "l"(a), "l"(b));
}
__device__ __forceinline__ u64 pack2(float lo, float hi) {
    u64 v; asm("mov.b64 %0, {%1, %2};" : "=l"(v) : "f"(lo), "f"(hi)); return v;
}
__device__ __forceinline__ void unpack2(u64 v, float& lo, float& hi) {
    asm("mov.b64 {%0, %1}, %2;" : "=f"(lo), "=f"(hi) : "l"(v));
}

// ---------------- weight transpose: make K the slow axis ----------------
#define PW_S1 (EDIM * 1024)                       // WtI
#define PW_S2 (PW_S1 + HDIM * 1024)               // WtR
#define PW_S3 (PW_S2 + EDIM * 1024)               // WtB
#define PW_S4 (PW_S3 + 512 * 2048)                // WtCin
#define PW_TOT (PW_S4 + 2 * 256 * 1024)           // WtChh

__global__ void prep_weights(const float* __restrict__ WihF, const float* __restrict__ WhhF,
                             const float* __restrict__ WihB,
                             const float* __restrict__ WihCf, const float* __restrict__ WihCb,
                             const float* __restrict__ WhhCf, const float* __restrict__ WhhCb)
{
    int stride = gridDim.x * blockDim.x;
    for (int idx = blockIdx.x * blockDim.x + threadIdx.x; idx < PW_TOT; idx += stride) {
        if (idx < PW_S1) {
            int k = idx >> 10, j = idx & 1023;
            g_WtI[idx] = WihF[j * EDIM + k];
        } else if (idx < PW_S2) {
            int r = idx - PW_S1;
            int k = r >> 10, j = r & 1023;
            g_WtR[r] = WhhF[j * HDIM + k];
        } else if (idx < PW_S3) {
            int r = idx - PW_S2;
            int k = r >> 10, j = r & 1023;
            g_WtB[r] = WihB[j * EDIM + k];
        } else if (idx < PW_S4) {
            int r = idx - PW_S3;
            int k = r >> 11, col = r & 2047;
            int d = col >> 10, j = col & 1023;
            g_WtCin[r] = (d ? WihCb : WihCf)[j * 512 + k];
        } else {
            int r = idx - PW_S4;
            int d = r >> 18;
            int rr = r & ((1 << 18) - 1);
            int k = rr >> 10, j = rr & 1023;
            g_WtChh[d][rr] = (d ? WhhCb : WhhCf)[j * HDIM + k];
        }
    }
}

// ---------------- counting sort by descending clen ----------------
__global__ void sort_kernel(const int* __restrict__ x_chunk_len)
{
    __shared__ int cnt[65];
    __shared__ int start[65];
    int tid = threadIdx.x;
    if (tid < 65) cnt[tid] = 0;
    __syncthreads();
    int c = x_chunk_len[tid];
    c = min(max(c, 1), TSTEPS);
    g_clen[tid] = c;
    atomicAdd(&cnt[c], 1);
    __syncthreads();
    if (tid == 0) {
        int s = 0;
        for (int v = TSTEPS; v >= 1; --v) { start[v] = s; s += cnt[v]; }
        g_active[0] = NSEQ;
        for (int t = 1; t < TSTEPS; ++t) g_active[t] = start[t];
    }
    __syncthreads();
    if (tid < 65) cnt[tid] = 0;
    __syncthreads();
    int p = start[c] + atomicAdd(&cnt[c], 1);
    g_order[p] = tid;
    g_sclen[p] = c;
}

// ---------------- zero state buffers (every call: graph replays) ----------
__global__ void init_zero()
{
    int idx0 = blockIdx.x * blockDim.x + threadIdx.x;
    int stride = gridDim.x * blockDim.x;
    if (idx0 < 16) g_rg_bar[idx0] = 0u;
    if (idx0 == 16) { g_chk_bar[0] = 0u; g_chk_bar[1] = 0u; }
    float* h0 = &g_hf[0][0];
    for (int i = idx0; i < 2 * NSEQ * HDIM; i += stride) h0[i] = 0.f;
    float* ch = &g_chh[0][0][0];
    for (int i = idx0; i < 2 * 2 * BATCH * HDIM; i += stride) ch[i] = 0.f;
}

// ---------------- gx = emb[x] @ WihF^T + b  (FFMA2, K-tile 32) — R12 known-good -------
// tile 64 rows x 128 cols; thread: 4 rows x 4 col-pairs (cols 2tx+32j)
__global__ void __launch_bounds__(256, 3) gx_gemm(
    const int* __restrict__ x, const float* __restrict__ emb,
    const float* __restrict__ bias)
{
    int t = blockIdx.z;
    int act = g_active[t];
    int row0 = blockIdx.y * 64;
    if (row0 >= act) return;
    int c0 = blockIdx.x * 128;

    __shared__ int s_tok[64];
    __shared__ float As[64][34];
    __shared__ float Bs[32][128];

    int tid = threadIdx.x;
    if (tid < 64) {
        int n = g_order[row0 + tid];
        s_tok[tid] = x[n * TSTEPS + t];
    }
    __syncthreads();

    int tx = tid & 15, ty = tid >> 4;
    u64 acc[4][4];
#pragma unroll
    for (int i = 0; i < 4; i++)
#pragma unroll
        for (int j = 0; j < 4; j++) acc[i][j] = 0ull;

    for (int k0 = 0; k0 < EDIM; k0 += 32) {
#pragma unroll
        for (int i = 0; i < 4; i++) {
            int idx = tid + i * 256;
            int r = idx >> 4, kp = idx & 15;
            int kg = k0 + 2 * kp;
            float2 v = make_float2(0.f, 0.f);
            if (kg < EDIM) v = *(const float2*)&emb[(size_t)s_tok[r] * EDIM + kg];
            As[r][2 * kp] = v.x;
            As[r][2 * kp + 1] = v.y;
        }
#pragma unroll
        for (int i = 0; i < 8; i++) {
            int idx = tid + i * 256;
            int k = idx >> 6, cp = idx & 63;
            int kg = k0 + k;
            float2 v = make_float2(0.f, 0.f);
            if (kg < EDIM) v = *(const float2*)&g_WtI[kg * 1024 + c0 + 2 * cp];
            Bs[k][2 * cp] = v.x;
            Bs[k][2 * cp + 1] = v.y;
        }
        __syncthreads();
#pragma unroll 2
        for (int k = 0; k < 32; k += 2) {
            u64 a0[4], a1[4];
#pragma unroll
            for (int i = 0; i < 4; i++) {
                float2 ap = *(const float2*)&As[4 * ty + i][k];
                a0[i] = pack2(ap.x, ap.x);
                a1[i] = pack2(ap.y, ap.y);
            }
#pragma unroll
            for (int j = 0; j < 4; j++) {
                u64 w0 = *(const u64*)&Bs[k][2 * tx + 32 * j];
                u64 w1 = *(const u64*)&Bs[k + 1][2 * tx + 32 * j];
#pragma unroll
                for (int i = 0; i < 4; i++) {
                    ffma2(acc[i][j], a0[i], w0);
                    ffma2(acc[i][j], a1[i], w1);
                }
            }
        }
        __syncthreads();
    }
#pragma unroll
    for (int i = 0; i < 4; i++) {
        int row = row0 + 4 * ty + i;
        float* dst = &g_gx[((size_t)t * 1024 + row) * 1024];
#pragma unroll
        for (int j = 0; j < 4; j++) {
            int col = c0 + 2 * tx + 32 * j;
            float lo, hi; unpack2(acc[i][j], lo, hi);
            *(float2*)&dst[col] = make_float2(lo + bias[col], hi + bias[col + 1]);
        }
    }
}

// ---------------- PERSISTENT token forward recurrence: per-row-group barriers ---------
// 256 CTAs = 16 row-groups (perm'd) x 16 u-blocks; one 64-row tile per CTA; c in regs.
// Step t+1 of a CTA reads only its own 64 rows of h, written by the 16 CTAs of the
// SAME row-group -> barrier only spans those 16 CTAs. Dead groups exit entirely,
// freeing their SM for the co-resident partner CTA.
__global__ void __launch_bounds__(256, 2) tok_persist()
{
    extern __shared__ u64 smdyn[];
    u64* ws = smdyn;                               // [k 256][combo 32] u64 = 64KB
    float* Asm = (float*)(smdyn + 8192);           // [2][64][36] h tiles (18.4KB)
    float* stage = Asm + 2 * 64 * 36;              // [64][68] gate staging (17.4KB)

    int cb = blockIdx.x & 15;
    int rg = c_perm[blockIdx.x >> 4];
    int row0 = rg * 64;
    int u0 = cb * 16;
    int tid = threadIdx.x;
    int ty4 = tid >> 4;        // 0..15 -> rows ty4*4..+3
    int txc = tid & 15;        // combos 2txc, 2txc+1

    // load weight pairs once: ws[k*32 + c], c=(g<<3)|up -> (W[k][g*256+u0+2up], +1)
    for (int idx = tid; idx < 8192; idx += 256) {
        int k = idx >> 5, c = idx & 31, g = c >> 3, up = c & 7;
        const float* sp = &g_WtR[k * 1024 + g * 256 + u0 + 2 * up];
        ws[idx] = pack2(sp[0], sp[1]);
    }
    // c-state registers, keyed to epilogue mapping: row=tid>>2, u-quad (tid&3)*4
    float creg[4];
#pragma unroll
    for (int j = 0; j < 4; j++) creg[j] = 0.f;
    __syncthreads();

    for (int t = 0; t < TSTEPS; t++) {
        int act = g_active[t];
        if (row0 >= act) break;   // act non-increasing: dead forever; whole group exits

        const float* __restrict__ hin = g_hf[t & 1];
        float* __restrict__ hout = g_hf[(t + 1) & 1];
        const float* __restrict__ gxt = &g_gx[(size_t)t * 1024 * 1024];

        u64 acc[4][2];
#pragma unroll
        for (int i = 0; i < 4; i++) { acc[i][0] = 0ull; acc[i][1] = 0ull; }

        // prefetch k-tile 0: 64 rows x 32 k
#pragma unroll
        for (int i = 0; i < 2; i++) {
            int idx = tid + i * 256;
            int r = idx >> 3, kq = idx & 7;
            float4 v = __ldcg((const float4*)&hin[(row0 + r) * HDIM + kq * 4]);
            *(float4*)&Asm[r * 36 + kq * 4] = v;
        }
        __syncthreads();

#pragma unroll 1
        for (int kt = 0; kt < 8; kt++) {
            float4 nxt[2];
            if (kt < 7) {
#pragma unroll
                for (int i = 0; i < 2; i++) {
                    int idx = tid + i * 256;
                    int r = idx >> 3, kq = idx & 7;
                    nxt[i] = __ldcg((const float4*)&hin[(row0 + r) * HDIM + (kt + 1) * 32 + kq * 4]);
                }
            }
            const float* Ab = &Asm[(kt & 1) * (64 * 36)];
            const u64* wk = &ws[kt * 1024];
#pragma unroll 8
            for (int kk = 0; kk < 32; kk++) {
                u64 a2[4];
#pragma unroll
                for (int i = 0; i < 4; i++) {
                    float a = Ab[(ty4 * 4 + i) * 36 + kk];
                    a2[i] = pack2(a, a);
                }
                ulonglong2 w2 = *(const ulonglong2*)&wk[kk * 32 + 2 * txc];
#pragma unroll
                for (int i = 0; i < 4; i++) {
                    ffma2(acc[i][0], a2[i], w2.x);
                    ffma2(acc[i][1], a2[i], w2.y);
                }
            }
            if (kt < 7) {
                float* d0 = &Asm[((kt + 1) & 1) * (64 * 36)];
#pragma unroll
                for (int i = 0; i < 2; i++) {
                    int idx = tid + i * 256;
                    int r = idx >> 3, kq = idx & 7;
                    *(float4*)&d0[r * 36 + kq * 4] = nxt[i];
                }
            }
            __syncthreads();
        }

        // stage: stage[row][g*16 + up*2] <- acc pairs
#pragma unroll
        for (int j = 0; j < 2; j++) {
            int c = 2 * txc + j;
            int g = c >> 3, up = c & 7;
            int col = g * 16 + up * 2;
#pragma unroll
            for (int i = 0; i < 4; i++)
                *(u64*)&stage[(ty4 * 4 + i) * 68 + col] = acc[i][j];
        }
        __syncthreads();

        // epilogue: thread -> row tid>>2, u-quad (tid&3)*4
        {
            int erow = tid >> 2;
            int p = row0 + erow;
            if (p < act) {
                int uq = (tid & 3) * 4;
                float4 gi4 = *(const float4*)&stage[erow * 68 + 0 * 16 + uq];
                float4 gf4 = *(const float4*)&stage[erow * 68 + 1 * 16 + uq];
                float4 gg4 = *(const float4*)&stage[erow * 68 + 2 * 16 + uq];
                float4 go4 = *(const float4*)&stage[erow * 68 + 3 * 16 + uq];
                const float* gxr = &gxt[(size_t)p * 1024];
                float4 bi = *(const float4*)&gxr[u0 + uq];
                float4 bf = *(const float4*)&gxr[256 + u0 + uq];
                float4 bg = *(const float4*)&gxr[512 + u0 + uq];
                float4 bo = *(const float4*)&gxr[768 + u0 + uq];
                float gi[4] = {gi4.x + bi.x, gi4.y + bi.y, gi4.z + bi.z, gi4.w + bi.w};
                float gf[4] = {gf4.x + bf.x, gf4.y + bf.y, gf4.z + bf.z, gf4.w + bf.w};
                float gg[4] = {gg4.x + bg.x, gg4.y + bg.y, gg4.z + bg.z, gg4.w + bg.w};
                float go[4] = {go4.x + bo.x, go4.y + bo.y, go4.z + bo.z, go4.w + bo.w};
                float4 hn;
                float* hv = (float*)&hn;
#pragma unroll
                for (int j = 0; j < 4; j++) {
                    float cn = sigf(gf[j]) * creg[j] + sigf(gi[j]) * tanhf(gg[j]);
                    hv[j] = sigf(go[j]) * tanhf(cn);
                    creg[j] = cn;
                }
                *(float4*)&hout[p * HDIM + u0 + uq] = hn;
            }
        }

        // per-row-group barrier: only the 16 CTAs sharing rg (they produce the h
        // this CTA reads next step). All group members are alive at t together.
        if (t < TSTEPS - 1) {
            __threadfence();
            __syncthreads();
            if (tid == 0) {
                atomicAdd(&g_rg_bar[rg], 1u);
                unsigned target = (unsigned)(t + 1) * 16u;
                while (*((volatile unsigned*)&g_rg_bar[rg]) < target) {}
            }
            __syncthreads();
        }
    }
}

// ---------------- token backward = ONE step from zero state at t = clen-1 -------------
__global__ void __launch_bounds__(256) tok_bwd(
    const int* __restrict__ x, const float* __restrict__ emb,
    const float* __restrict__ bias)
{
    int row0 = blockIdx.x * 32;
    int u0 = blockIdx.y * 64;
    __shared__ float As[32][33];
    __shared__ float Ws[4][32][64];
    __shared__ int s_tok[32];
    int tid = threadIdx.x;
    if (tid < 32) {
        int n = row0 + tid;
        int c = g_clen[n];
        s_tok[tid] = x[n * TSTEPS + (c - 1)];
    }
    __syncthreads();
    int tx = tid & 15, ty = tid >> 4;
    float acc[2][4][4];
#pragma unroll
    for (int r = 0; r < 2; r++)
#pragma unroll
        for (int q = 0; q < 4; q++)
#pragma unroll
            for (int j = 0; j < 4; j++) acc[r][q][j] = 0.f;

    for (int k0 = 0; k0 < EDIM; k0 += 32) {
#pragma unroll
        for (int i = 0; i < 4; i++) {
            int idx = tid + i * 256;
            int r = idx >> 5, kl = idx & 31;
            int kg = k0 + kl;
            As[r][kl] = (kg < EDIM) ? emb[(size_t)s_tok[r] * EDIM + kg] : 0.f;
        }
#pragma unroll
        for (int i = 0; i < 32; i++) {
            int idx = tid + i * 256;
            int q = idx >> 11;
            int rem = idx & 2047;
            int kl = rem >> 6, u = rem & 63;
            int kg = k0 + kl;
            Ws[q][kl][u] = (kg < EDIM) ? g_WtB[kg * 1024 + q * 256 + u0 + u] : 0.f;
        }
        __syncthreads();
#pragma unroll
        for (int k = 0; k < 32; k++) {
            float a0 = As[2 * ty][k];
            float a1 = As[2 * ty + 1][k];
#pragma unroll
            for (int q = 0; q < 4; q++) {
                float4 w = *(const float4*)&Ws[q][k][tx * 4];
                acc[0][q][0] += a0 * w.x; acc[0][q][1] += a0 * w.y;
                acc[0][q][2] += a0 * w.z; acc[0][q][3] += a0 * w.w;
                acc[1][q][0] += a1 * w.x; acc[1][q][1] += a1 * w.y;
                acc[1][q][2] += a1 * w.z; acc[1][q][3] += a1 * w.w;
            }
        }
        __syncthreads();
    }

#pragma unroll
    for (int rr = 0; rr < 2; rr++) {
        int n = row0 + 2 * ty + rr;
#pragma unroll
        for (int j = 0; j < 4; j++) {
            int u = u0 + tx * 4 + j;
            float gi = acc[rr][0][j] + bias[u];
            float gg = acc[rr][2][j] + bias[512 + u];
            float go = acc[rr][3][j] + bias[768 + u];
            float cn = sigf(gi) * tanhf(gg);
            float hn = sigf(go) * tanhf(cn);
            g_tok_last[n * 512 + 256 + u] = hn;
        }
    }
}

// ---------------- scatter forward finals back to original order ----------------------
__global__ void tok_fwd_readout()
{
    int p = blockIdx.x;
    int u = threadIdx.x;
    int n = g_order[p];
    int cl = g_sclen[p];
    g_tok_last[n * 512 + u] = g_hf[cl & 1][p * HDIM + u];
}

// ---------------- chunk-level input projection: [1024,512] x [512,2048] --------------
__global__ void __launch_bounds__(256) chunk_inproj(
    const float* __restrict__ bcf, const float* __restrict__ bcb)
{
    int row0 = blockIdx.x * 64;
    int c0 = blockIdx.y * 64;
    __shared__ float As[64][17];
    __shared__ float Bs[16][64];
    int tid = threadIdx.x;
    int tx = tid & 15, ty = tid >> 4;
    float acc[4][4];
#pragma unroll
    for (int i = 0; i < 4; i++)
#pragma unroll
        for (int j = 0; j < 4; j++) acc[i][j] = 0.f;

    for (int k0 = 0; k0 < 512; k0 += 16) {
#pragma unroll
        for (int i = 0; i < 4; i++) {
            int idx = tid + i * 256;
            int r = idx >> 4, kl = idx & 15;
            As[r][kl] = g_tok_last[(row0 + r) * 512 + k0 + kl];
        }
#pragma unroll
        for (int i = 0; i < 4; i++) {
            int idx = tid + i * 256;
            int kl = idx >> 6, c = idx & 63;
            Bs[kl][c] = g_WtCin[(k0 + kl) * 2048 + c0 + c];
        }
        __syncthreads();
#pragma unroll
        for (int k = 0; k < 16; k++) {
            float a[4];
#pragma unroll
            for (int i = 0; i < 4; i++) a[i] = As[4 * ty + i][k];
            float4 w = *(const float4*)&Bs[k][tx * 4];
#pragma unroll
            for (int i = 0; i < 4; i++) {
                acc[i][0] += a[i] * w.x; acc[i][1] += a[i] * w.y;
                acc[i][2] += a[i] * w.z; acc[i][3] += a[i] * w.w;
            }
        }
        __syncthreads();
    }
#pragma unroll
    for (int i = 0; i < 4; i++) {
        int row = row0 + 4 * ty + i;
#pragma unroll
        for (int j = 0; j < 4; j++) {
            int col = c0 + tx * 4 + j;
            int jj = col & 1023;
            float b = (col >> 10) ? bcb[jj] : bcf[jj];
            g_gxc[row * 2048 + col] = acc[i][j] + b;
        }
    }
}

// ---------------- PERSISTENT chunk BiLSTM (per-direction barriers) --------------------
__global__ void __launch_bounds__(256) chunk_persist(const int* __restrict__ x_len)
{
    extern __shared__ u64 smdyn[];
    u64* ws = smdyn;                       // [k][g][up] (64KB)
    float* Asm = (float*)(smdyn + 8192);   // [32][257] full h (32.9KB)

    int d = blockIdx.x >> 4;
    int cb = blockIdx.x & 15;
    int u0 = cb * 16;
    int tid = threadIdx.x;
    int tx = tid & 7;
    int ty = tid >> 3;    // batch row 0..31

    for (int idx = tid; idx < 8192; idx += 256) {
        int k = idx >> 5, rem = idx & 31, g = rem >> 3, up = rem & 7;
        const float* sp = &g_WtChh[d][k * 1024 + g * 256 + u0 + 2 * up];
        ws[idx] = pack2(sp[0], sp[1]);
    }
    int len = x_len[ty];
    float c0r = 0.f, c1r = 0.f;
    __syncthreads();

    for (int s = 0; s < LCH; s++) {
        int t_d = d ? (LCH - 1 - s) : s;
        const float* __restrict__ hin = g_chh[d][s & 1];
        float* __restrict__ hout = g_chh[d][(s + 1) & 1];

#pragma unroll
        for (int i = 0; i < 8; i++) {
            int idx = tid + i * 256;
            int b = idx >> 6, kq = idx & 63;
            float4 v = __ldcg((const float4*)&hin[b * HDIM + kq * 4]);
            float* dp = &Asm[b * 257 + kq * 4];
            dp[0] = v.x; dp[1] = v.y; dp[2] = v.z; dp[3] = v.w;
        }
        __syncthreads();

        u64 acc[4] = {0ull, 0ull, 0ull, 0ull};
#pragma unroll 8
        for (int k = 0; k < 256; k++) {
            float a = Asm[ty * 257 + k];
            u64 a2 = pack2(a, a);
#pragma unroll
            for (int g = 0; g < 4; g++) ffma2(acc[g], a2, ws[k * 32 + g * 8 + tx]);
        }

        int ub = u0 + 2 * tx;
        bool actv = (t_d < len);
        float gi0, gi1, gf0, gf1, gg0, gg1, go0, go1;
        unpack2(acc[0], gi0, gi1);
        unpack2(acc[1], gf0, gf1);
        unpack2(acc[2], gg0, gg1);
        unpack2(acc[3], go0, go1);
        const float* gxr = &g_gxc[(ty * LCH + t_d) * 2048 + d * 1024];
        float2 bi = *(const float2*)&gxr[ub];
        float2 bf = *(const float2*)&gxr[256 + ub];
        float2 bg = *(const float2*)&gxr[512 + ub];
        float2 bo = *(const float2*)&gxr[768 + ub];
        gi0 += bi.x; gi1 += bi.y; gf0 += bf.x; gf1 += bf.y;
        gg0 += bg.x; gg1 += bg.y; go0 += bo.x; go1 += bo.y;
        float hp0 = Asm[ty * 257 + ub], hp1 = Asm[ty * 257 + ub + 1];
        float hn0 = hp0, hn1 = hp1, o0 = 0.f, o1 = 0.f;
        if (actv) {
            float cn0 = sigf(gf0) * c0r + sigf(gi0) * tanhf(gg0);
            float cn1 = sigf(gf1) * c1r + sigf(gi1) * tanhf(gg1);
            hn0 = sigf(go0) * tanhf(cn0);
            hn1 = sigf(go1) * tanhf(cn1);
            c0r = cn0; c1r = cn1;
            o0 = hn0; o1 = hn1;
        }
        *(float2*)&hout[ty * HDIM + ub] = make_float2(hn0, hn1);
        *(float2*)&g_chout[(ty * LCH + t_d) * 512 + d * 256 + ub] = make_float2(o0, o1);

        // per-direction barrier: the two directions never share data
        if (s < LCH - 1) {
            __threadfence();
            __syncthreads();
            if (tid == 0) {
                atomicAdd(&g_chk_bar[d], 1u);
                unsigned target = (unsigned)(s + 1) * 16u;
                while (*((volatile unsigned*)&g_chk_bar[d]) < target) {}
            }
            __syncthreads();
        }
    }
}

// ---------------- final FC: [1024,512] x [512,9] -------------------------------------
__global__ void fc_kernel(const float* __restrict__ fcW, const float* __restrict__ fcb,
                          float* __restrict__ out)
{
    int row = blockIdx.x * 8 + (threadIdx.x >> 5);
    int lane = threadIdx.x & 31;
    if (row >= NSEQ) return;
    const float* v = &g_chout[row * 512];
#pragma unroll
    for (int k = 0; k < NTAG; k++) {
        float sum = 0.f;
        for (int dd = lane; dd < 512; dd += 32) sum += v[dd] * fcW[k * 512 + dd];
#pragma unroll
        for (int o = 16; o; o >>= 1) sum += __shfl_xor_sync(0xffffffffu, sum, o);
        if (lane == 0) out[row * NTAG + k] = sum + fcb[k];
    }
}

// ---------------- launch --------------------------------------------------------------
#define TOK_SMEM (65536 + 2 * 64 * 36 * 4 + 64 * 68 * 4)   // 101376 (x2 = 198K < 228K/SM)
#define CHK_SMEM (65536 + 32 * 257 * 4)                    // 98432

extern "C" void kernel_launch(void* const* d_in, const int* in_sizes, int n_in,
                              void* d_out, int out_size)
{
    const int*   x           = (const int*)d_in[0];
    const int*   x_len       = (const int*)d_in[2];
    const int*   x_chunk_len = (const int*)d_in[3];
    const float* emb         = (const float*)d_in[4];
    const float* tok_Wih_f   = (const float*)d_in[5];
    const float* tok_Whh_f   = (const float*)d_in[6];
    const float* tok_b_f     = (const float*)d_in[7];
    const float* tok_Wih_b   = (const float*)d_in[8];
    const float* tok_b_b     = (const float*)d_in[10];
    const float* chk_Wih_f   = (const float*)d_in[11];
    const float* chk_Whh_f   = (const float*)d_in[12];
    const float* chk_b_f     = (const float*)d_in[13];
    const float* chk_Wih_b   = (const float*)d_in[14];
    const float* chk_Whh_b   = (const float*)d_in[15];
    const float* chk_b_b     = (const float*)d_in[16];
    const float* fc_W        = (const float*)d_in[17];
    const float* fc_b        = (const float*)d_in[18];
    float* out = (float*)d_out;

    cudaFuncSetAttribute(tok_persist, cudaFuncAttributeMaxDynamicSharedMemorySize, TOK_SMEM);
    cudaFuncSetAttribute(chunk_persist, cudaFuncAttributeMaxDynamicSharedMemorySize, CHK_SMEM);

    prep_weights<<<2048, 256>>>(tok_Wih_f, tok_Whh_f, tok_Wih_b,
                                chk_Wih_f, chk_Wih_b, chk_Whh_f, chk_Whh_b);
    sort_kernel<<<1, 1024>>>(x_chunk_len);
    init_zero<<<512, 256>>>();

    // Input projections for all active (row, t) pairs (parallel over t).
    gx_gemm<<<dim3(8, 16, 64), 256>>>(x, emb, tok_b_f);

    // Entire 64-step forward recurrence: 256 CTAs, 2/SM, per-row-group barriers.
    tok_persist<<<TOK_CTAS, 256, TOK_SMEM>>>();

    tok_fwd_readout<<<NSEQ, 256>>>();
    tok_bwd<<<dim3(32, 4), 256>>>(x, emb, tok_b_b);

    chunk_inproj<<<dim3(16, 32), 256>>>(chk_b_f, chk_b_b);

    // Entire 32-step chunk BiLSTM (both dirs) in ONE persistent kernel.
    chunk_persist<<<CHK_CTAS, 256, CHK_SMEM>>>(x_len);

    fc_kernel<<<128, 256>>>(fc_W, fc_b, out);
}